// round 15
// baseline (speedup 1.0000x reference)
#include <cuda_runtime.h>
#include <cuda_bf16.h>
#include <cuda_fp16.h>
#include <math.h>
#include <stdint.h>

// Problem dims
#define NB   2048
#define NH   16384
#define NE   64
#define DIN  384
#define NKD  128
#define NVD  128
#define NHD  256
#define NSPLIT_G 8
#define NSPLIT_AH 16
#define NT   12288        // S cols on tensor pipe
#define NF   (NH - NT)    // S cols on FFMA pipe (4096)

typedef __nv_bfloat16 bf16;
typedef __half fp16;

// ---------------- scratch (device globals) ----------------
__device__ float g_k[NB*NKD];
__device__ float g_v[NB*NVD];
__device__ float g_h[NB*NHD];
__device__ float g_dpred[NB*NVD];
__device__ float g_dh[NB*NHD];
__device__ float g_gW1p[NSPLIT_G*NHD*NKD];
__device__ float g_gW2p[NSPLIT_G*NVD*NHD];
__device__ float g_gW1[NHD*NKD];
__device__ float g_gb1[NHD];
__device__ float g_gW2[NVD*NHD];
__device__ float g_gb2[NVD];
__device__ float g_nW1[NHD*NKD];
__device__ float g_nb1[NHD];
__device__ float g_nW2[NVD*NHD];
__device__ float g_nb2[NVD];
__device__ float g_h2[NB*NHD];
__device__ float g_ctx[NB*NVD];
__device__ float g_S[33554432];            // 2048*16384 fp32
__device__ float g_aop[NSPLIT_AH*NB*NVD];
__device__ float g_st[NB*NVD];
__device__ float g_WT[DIN*DIN];            // W'^T = Wk^T @ Wq (fp32)
__device__ float g_qf[NB*DIN];             // q' fp32 (exact)
__device__ float g_theta[1];
__device__ float g_ectx[NVD];
__device__ float g_eg[1];
// split operands
__device__ bf16 g_Wsth[NVD*DIN], g_Wstl[NVD*DIN];
__device__ bf16 g_histh[NH*DIN], g_histl[NH*DIN];
__device__ fp16 g_hwTh[(size_t)NVD*NH];                          // (Wst @ hist^T) fp16
__device__ bf16 g_qh[NB*DIN],   g_ql[NB*DIN];                    // q' bf16 hi/lo
__device__ fp16 g_attnP[(size_t)NB*NH];                          // P fp16

// ================= HMMA (mma.sync) GEMM =================
// AMODE 0: C = Ah@Bh^T + Ah@Bl^T + Al@Bh^T (bf16 3-term)
// AMODE 2: C = A@Bh^T                      (fp16 1-term, A,B unsplit)
// WMODE 0: fp32 -> Cf + z*M*N; 3: fp16 hi only
#define TILE_B   10240
#define STAGE_B  (4*TILE_B)
#define NSTAGE   3
#define HM_SMEM  (NSTAGE*STAGE_B)   // 122880

__device__ __forceinline__ uint32_t smem_u32(const void* p) {
    uint32_t a;
    asm("{ .reg .u64 t; cvta.to.shared.u64 t, %1; cvt.u32.u64 %0, t; }" : "=r"(a) : "l"(p));
    return a;
}
__device__ __forceinline__ void cp16(uint32_t s, const void* g) {
    asm volatile("cp.async.cg.shared.global [%0], [%1], 16;" :: "r"(s), "l"(g));
}
__device__ __forceinline__ void cp_commit() {
    asm volatile("cp.async.commit_group;" ::: "memory");
}
template<int N>
__device__ __forceinline__ void cp_wait() {
    asm volatile("cp.async.wait_group %0;" :: "n"(N) : "memory");
}
__device__ __forceinline__ void ldsm4(uint32_t* r, uint32_t addr) {
    asm volatile("ldmatrix.sync.aligned.m8n8.x4.shared.b16 {%0,%1,%2,%3}, [%4];"
                 : "=r"(r[0]), "=r"(r[1]), "=r"(r[2]), "=r"(r[3]) : "r"(addr));
}
__device__ __forceinline__ void ldsm2(uint32_t* r, uint32_t addr) {
    asm volatile("ldmatrix.sync.aligned.m8n8.x2.shared.b16 {%0,%1}, [%2];"
                 : "=r"(r[0]), "=r"(r[1]) : "r"(addr));
}
__device__ __forceinline__ void mma_bf16(float* c, const uint32_t* a, const uint32_t* b) {
    asm volatile(
        "mma.sync.aligned.m16n8k16.row.col.f32.bf16.bf16.f32 "
        "{%0,%1,%2,%3}, {%4,%5,%6,%7}, {%8,%9}, {%0,%1,%2,%3};"
        : "+f"(c[0]), "+f"(c[1]), "+f"(c[2]), "+f"(c[3])
        : "r"(a[0]), "r"(a[1]), "r"(a[2]), "r"(a[3]), "r"(b[0]), "r"(b[1]));
}
__device__ __forceinline__ void mma_f16(float* c, const uint32_t* a, const uint32_t* b) {
    asm volatile(
        "mma.sync.aligned.m16n8k16.row.col.f32.f16.f16.f32 "
        "{%0,%1,%2,%3}, {%4,%5,%6,%7}, {%8,%9}, {%0,%1,%2,%3};"
        : "+f"(c[0]), "+f"(c[1]), "+f"(c[2]), "+f"(c[3])
        : "r"(a[0]), "r"(a[1]), "r"(a[2]), "r"(a[3]), "r"(b[0]), "r"(b[1]));
}

template<int WMODE, int AMODE>
__global__ void __launch_bounds__(512, 1) hmma_gemm(
    const bf16* __restrict__ Ah, const bf16* __restrict__ Al,
    const bf16* __restrict__ Bh, const bf16* __restrict__ Bl,
    float* __restrict__ Cf, unsigned short* __restrict__ Ch,
    int M, int N, int K, int Kchunk, int moff)
{
    extern __shared__ char smem[];
    const int tid = threadIdx.x, wid = tid >> 5, lid = tid & 31;
    const int wm = wid >> 2, wn = wid & 3;
    const int g = lid >> 2, t = lid & 3;
    const int n0 = blockIdx.x * 128, m0 = blockIdx.y * 128 + moff;
    const int kbeg = blockIdx.z * Kchunk;
    const int iters = Kchunk / 32;

    const uint32_t sb = smem_u32(smem);
    const bf16* srcs[4] = { Ah, Al, Bh, Bl };
    const int   rows[4] = { m0, m0, n0, n0 };

    const uint32_t a_off = (uint32_t)((wm*32 + (lid & 15)) * 80 + (lid >> 4) * 16);
    const uint32_t b_off = (uint32_t)((wn*32 + (lid & 7))  * 80 + ((lid >> 3) & 1) * 16);

    const int l_row = tid >> 2, l_ch = tid & 3;

    auto load_stage = [&](int stage, int k0) {
        uint32_t base = sb + stage * STAGE_B + l_row*80 + l_ch*16;
        size_t goff = (size_t)l_row * K + k0 + l_ch*8;
        #pragma unroll
        for (int tile = 0; tile < 4; tile++) {
            if (AMODE == 2 && (tile == 1 || tile == 3)) continue;
            cp16(base + tile*TILE_B, srcs[tile] + (size_t)rows[tile]*K + goff);
        }
    };

    float acc[2][4][4];
    #pragma unroll
    for (int a = 0; a < 2; a++)
        #pragma unroll
        for (int b = 0; b < 4; b++)
            #pragma unroll
            for (int c = 0; c < 4; c++) acc[a][b][c] = 0.f;

    load_stage(0, kbeg);
    cp_commit();
    if (iters > 1) load_stage(1, kbeg + 32);
    cp_commit();

    for (int it = 0; it < iters; it++) {
        cp_wait<1>();
        __syncthreads();
        if (it + 2 < iters) load_stage((it + 2) % NSTAGE, kbeg + (it + 2) * 32);
        cp_commit();

        const uint32_t stb = sb + (it % NSTAGE) * STAGE_B;
        #pragma unroll
        for (int kb = 0; kb < 2; kb++) {
            const uint32_t ko = kb * 32;
            uint32_t ah[2][4], al[2][4], bh[4][2], bl[4][2];
            #pragma unroll
            for (int mf = 0; mf < 2; mf++) {
                ldsm4(ah[mf], stb + a_off + mf*(16*80) + ko);
                if (AMODE == 0) ldsm4(al[mf], stb + TILE_B + a_off + mf*(16*80) + ko);
            }
            #pragma unroll
            for (int nf = 0; nf < 4; nf++) {
                ldsm2(bh[nf], stb + 2*TILE_B + b_off + nf*(8*80) + ko);
                if (AMODE == 0) ldsm2(bl[nf], stb + 3*TILE_B + b_off + nf*(8*80) + ko);
            }
            #pragma unroll
            for (int mf = 0; mf < 2; mf++)
                #pragma unroll
                for (int nf = 0; nf < 4; nf++) {
                    if (AMODE == 0) mma_bf16(acc[mf][nf], ah[mf], bh[nf]);
                    else            mma_f16 (acc[mf][nf], ah[mf], bh[nf]);
                }
            if (AMODE == 0) {
                #pragma unroll
                for (int mf = 0; mf < 2; mf++)
                    #pragma unroll
                    for (int nf = 0; nf < 4; nf++)
                        mma_bf16(acc[mf][nf], ah[mf], bl[nf]);
                #pragma unroll
                for (int mf = 0; mf < 2; mf++)
                    #pragma unroll
                    for (int nf = 0; nf < 4; nf++)
                        mma_bf16(acc[mf][nf], al[mf], bh[nf]);
            }
        }
    }

    #pragma unroll
    for (int mf = 0; mf < 2; mf++) {
        #pragma unroll
        for (int nf = 0; nf < 4; nf++) {
            int row0 = m0 + wm*32 + mf*16 + g;
            int col  = n0 + wn*32 + nf*8 + 2*t;
            float* c = acc[mf][nf];
            if (WMODE == 3) {
                fp16 h0 = __float2half(c[0]), h1 = __float2half(c[1]);
                fp16 h2 = __float2half(c[2]), h3 = __float2half(c[3]);
                ushort2 u0, v0;
                u0.x = *(unsigned short*)&h0; u0.y = *(unsigned short*)&h1;
                v0.x = *(unsigned short*)&h2; v0.y = *(unsigned short*)&h3;
                *(ushort2*)&Ch[(size_t)row0 * N + col]     = u0;
                *(ushort2*)&Ch[(size_t)(row0+8) * N + col] = v0;
            } else {
                float* Co = Cf + (size_t)blockIdx.z * M * N;
                *(float2*)&Co[(size_t)row0 * N + col]     = make_float2(c[0], c[1]);
                *(float2*)&Co[(size_t)(row0+8) * N + col] = make_float2(c[2], c[3]);
            }
        }
    }
}

// ================= conversion kernel (bf16 split) =================
__global__ void split_k(const float* __restrict__ in, bf16* __restrict__ hi,
                        bf16* __restrict__ lo, int n)
{
    int i = blockIdx.x * 256 + threadIdx.x;
    if (i < n) {
        float v = in[i];
        bf16 h = __float2bfloat16(v);
        hi[i] = h;
        lo[i] = __float2bfloat16(v - __bfloat162float(h));
    }
}

// ================= FFMA GEMMs =================
template<bool BIAS, bool RELU, bool DPRED>
__launch_bounds__(256)
__global__ void gemm_abT(const float* __restrict__ A, const float* __restrict__ Bm,
                         const float* __restrict__ bias, const float* __restrict__ Vm,
                         float dscale, float* __restrict__ C,
                         int M, int N, int K)
{
    __shared__ float As[16][64];
    __shared__ float Bs[16][64];
    const int t  = threadIdx.x;
    const int tx = t & 15, ty = t >> 4;
    const int m0 = blockIdx.y * 64, n0 = blockIdx.x * 64;
    const int lr = t >> 2;
    const int lc = (t & 3) << 2;
    float acc[4][4] = {};
    const float* Ag = A  + (size_t)(m0 + lr) * K + lc;
    const float* Bg = Bm + (size_t)(n0 + lr) * K + lc;
    for (int k0 = 0; k0 < K; k0 += 16) {
        float4 a4 = *(const float4*)(Ag + k0);
        float4 b4 = *(const float4*)(Bg + k0);
        As[lc+0][lr]=a4.x; As[lc+1][lr]=a4.y; As[lc+2][lr]=a4.z; As[lc+3][lr]=a4.w;
        Bs[lc+0][lr]=b4.x; Bs[lc+1][lr]=b4.y; Bs[lc+2][lr]=b4.z; Bs[lc+3][lr]=b4.w;
        __syncthreads();
        #pragma unroll
        for (int kk = 0; kk < 16; kk++) {
            float4 av = *(const float4*)&As[kk][ty<<2];
            float4 bv = *(const float4*)&Bs[kk][tx<<2];
            acc[0][0]+=av.x*bv.x; acc[0][1]+=av.x*bv.y; acc[0][2]+=av.x*bv.z; acc[0][3]+=av.x*bv.w;
            acc[1][0]+=av.y*bv.x; acc[1][1]+=av.y*bv.y; acc[1][2]+=av.y*bv.z; acc[1][3]+=av.y*bv.w;
            acc[2][0]+=av.z*bv.x; acc[2][1]+=av.z*bv.y; acc[2][2]+=av.z*bv.z; acc[2][3]+=av.z*bv.w;
            acc[3][0]+=av.w*bv.x; acc[3][1]+=av.w*bv.y; acc[3][2]+=av.w*bv.z; acc[3][3]+=av.w*bv.w;
        }
        __syncthreads();
    }
    #pragma unroll
    for (int u = 0; u < 4; u++) {
        const int m = m0 + (ty<<2) + u;
        float4 o;
        float* oc = (float*)&o;
        #pragma unroll
        for (int v = 0; v < 4; v++) {
            const int n = n0 + (tx<<2) + v;
            float val = acc[u][v];
            if (BIAS) val += bias[n];
            if (RELU) val = fmaxf(val, 0.f);
            if (DPRED) val = (val - Vm[(size_t)m * N + n]) * dscale;
            oc[v] = val;
        }
        *(float4*)&C[(size_t)m * N + n0 + (tx<<2)] = o;
    }
}

// S-slice FFMA GEMM: C[m, noff+n] = A[m,:] @ B[noff+n,:]^T, C row stride ldc
__launch_bounds__(256)
__global__ void gemm_abT_s(const float* __restrict__ A, const float* __restrict__ Bm,
                           float* __restrict__ C, int ldc, int K, int noff, int moff)
{
    __shared__ float As[16][64];
    __shared__ float Bs[16][64];
    const int t  = threadIdx.x;
    const int tx = t & 15, ty = t >> 4;
    const int m0 = blockIdx.y * 64 + moff, n0 = blockIdx.x * 64 + noff;
    const int lr = t >> 2;
    const int lc = (t & 3) << 2;
    float acc[4][4] = {};
    const float* Ag = A  + (size_t)(m0 + lr) * K + lc;
    const float* Bg = Bm + (size_t)(n0 + lr) * K + lc;
    for (int k0 = 0; k0 < K; k0 += 16) {
        float4 a4 = *(const float4*)(Ag + k0);
        float4 b4 = *(const float4*)(Bg + k0);
        As[lc+0][lr]=a4.x; As[lc+1][lr]=a4.y; As[lc+2][lr]=a4.z; As[lc+3][lr]=a4.w;
        Bs[lc+0][lr]=b4.x; Bs[lc+1][lr]=b4.y; Bs[lc+2][lr]=b4.z; Bs[lc+3][lr]=b4.w;
        __syncthreads();
        #pragma unroll
        for (int kk = 0; kk < 16; kk++) {
            float4 av = *(const float4*)&As[kk][ty<<2];
            float4 bv = *(const float4*)&Bs[kk][tx<<2];
            acc[0][0]+=av.x*bv.x; acc[0][1]+=av.x*bv.y; acc[0][2]+=av.x*bv.z; acc[0][3]+=av.x*bv.w;
            acc[1][0]+=av.y*bv.x; acc[1][1]+=av.y*bv.y; acc[1][2]+=av.y*bv.z; acc[1][3]+=av.y*bv.w;
            acc[2][0]+=av.z*bv.x; acc[2][1]+=av.z*bv.y; acc[2][2]+=av.z*bv.z; acc[2][3]+=av.z*bv.w;
            acc[3][0]+=av.w*bv.x; acc[3][1]+=av.w*bv.y; acc[3][2]+=av.w*bv.z; acc[3][3]+=av.w*bv.w;
        }
        __syncthreads();
    }
    #pragma unroll
    for (int u = 0; u < 4; u++) {
        float4 o = make_float4(acc[u][0], acc[u][1], acc[u][2], acc[u][3]);
        *(float4*)&C[(size_t)(m0 + (ty<<2) + u) * ldc + n0 + (tx<<2)] = o;
    }
}

template<bool MASK>
__launch_bounds__(256)
__global__ void gemm_ab(const float* __restrict__ A, const float* __restrict__ Bm,
                        const float* __restrict__ mask, float* __restrict__ C,
                        int M, int N, int K, int Kchunk)
{
    __shared__ float As[16][64];
    __shared__ float Bs[16][64];
    const int t  = threadIdx.x;
    const int tx = t & 15, ty = t >> 4;
    const int m0 = blockIdx.y * 64, n0 = blockIdx.x * 64;
    const int kbeg = blockIdx.z * Kchunk, kend = kbeg + Kchunk;
    const int lrA = t >> 2,  lcA = (t & 3)  << 2;
    const int lrB = t >> 4,  lcB = (t & 15) << 2;
    float acc[4][4] = {};
    for (int k0 = kbeg; k0 < kend; k0 += 16) {
        float4 a4 = *(const float4*)&A [(size_t)(m0 + lrA) * K + k0 + lcA];
        float4 b4 = *(const float4*)&Bm[(size_t)(k0 + lrB) * N + n0 + lcB];
        As[lcA+0][lrA]=a4.x; As[lcA+1][lrA]=a4.y; As[lcA+2][lrA]=a4.z; As[lcA+3][lrA]=a4.w;
        *(float4*)&Bs[lrB][lcB] = b4;
        __syncthreads();
        #pragma unroll
        for (int kk = 0; kk < 16; kk++) {
            float4 av = *(const float4*)&As[kk][ty<<2];
            float4 bv = *(const float4*)&Bs[kk][tx<<2];
            acc[0][0]+=av.x*bv.x; acc[0][1]+=av.x*bv.y; acc[0][2]+=av.x*bv.z; acc[0][3]+=av.x*bv.w;
            acc[1][0]+=av.y*bv.x; acc[1][1]+=av.y*bv.y; acc[1][2]+=av.y*bv.z; acc[1][3]+=av.y*bv.w;
            acc[2][0]+=av.z*bv.x; acc[2][1]+=av.z*bv.y; acc[2][2]+=av.z*bv.z; acc[2][3]+=av.z*bv.w;
            acc[3][0]+=av.w*bv.x; acc[3][1]+=av.w*bv.y; acc[3][2]+=av.w*bv.z; acc[3][3]+=av.w*bv.w;
        }
        __syncthreads();
    }
    float* Co = C + (size_t)blockIdx.z * M * N;
    #pragma unroll
    for (int u = 0; u < 4; u++) {
        const int m = m0 + (ty<<2) + u;
        float4 o;
        float* oc = (float*)&o;
        #pragma unroll
        for (int v = 0; v < 4; v++) {
            float val = acc[u][v];
            if (MASK) val = (mask[(size_t)m * N + n0 + (tx<<2) + v] > 0.f) ? val : 0.f;
            oc[v] = val;
        }
        *(float4*)&Co[(size_t)m * N + n0 + (tx<<2)] = o;
    }
}

__launch_bounds__(256)
__global__ void gemm_aTb(const float* __restrict__ A, const float* __restrict__ Bm,
                         float* __restrict__ Cpart, int L, int M, int N, int Lchunk)
{
    __shared__ float As[16][64];
    __shared__ float Bs[16][64];
    const int t  = threadIdx.x;
    const int tx = t & 15, ty = t >> 4;
    const int m0 = blockIdx.y * 64, n0 = blockIdx.x * 64;
    const int l0b = blockIdx.z * Lchunk;
    const int lr = t >> 4, lc4 = (t & 15) << 2;
    float acc[4][4] = {};
    for (int l0 = l0b; l0 < l0b + Lchunk; l0 += 16) {
        *(float4*)&As[lr][lc4] = *(const float4*)&A [(size_t)(l0 + lr) * M + m0 + lc4];
        *(float4*)&Bs[lr][lc4] = *(const float4*)&Bm[(size_t)(l0 + lr) * N + n0 + lc4];
        __syncthreads();
        #pragma unroll
        for (int kk = 0; kk < 16; kk++) {
            float4 av = *(const float4*)&As[kk][ty<<2];
            float4 bv = *(const float4*)&Bs[kk][tx<<2];
            acc[0][0]+=av.x*bv.x; acc[0][1]+=av.x*bv.y; acc[0][2]+=av.x*bv.z; acc[0][3]+=av.x*bv.w;
            acc[1][0]+=av.y*bv.x; acc[1][1]+=av.y*bv.y; acc[1][2]+=av.y*bv.z; acc[1][3]+=av.y*bv.w;
            acc[2][0]+=av.z*bv.x; acc[2][1]+=av.z*bv.y; acc[2][2]+=av.z*bv.z; acc[2][3]+=av.z*bv.w;
            acc[3][0]+=av.w*bv.x; acc[3][1]+=av.w*bv.y; acc[3][2]+=av.w*bv.z; acc[3][3]+=av.w*bv.w;
        }
        __syncthreads();
    }
    float* Co = Cpart + (size_t)blockIdx.z * M * N;
    #pragma unroll
    for (int u = 0; u < 4; u++) {
        float4 o;
        float* oc = (float*)&o;
        #pragma unroll
        for (int v = 0; v < 4; v++) oc[v] = acc[u][v];
        *(float4*)&Co[(size_t)(m0 + (ty<<2) + u) * N + n0 + (tx<<2)] = o;
    }
}

// ================= small kernels =================
__global__ void combine_k(const float* __restrict__ parts, float* __restrict__ out,
                          int len, int np)
{
    int i = blockIdx.x * 256 + threadIdx.x;
    if (i < len) {
        float s = 0.f;
        for (int p = 0; p < np; p++) s += parts[(size_t)p * len + i];
        out[i] = s;
    }
}

__global__ void colsum_k(const float* __restrict__ A, float* __restrict__ out, int rows, int N)
{
    int c = threadIdx.x;
    float s = 0.f;
    for (int r = 0; r < rows; r++) s += A[(size_t)r * N + c];
    out[c] = s;
}

__global__ void surprise_k()
{
    __shared__ float red[256];
    int t = threadIdx.x;
    float s = 0.f;
    for (int i = t; i < NHD*NKD; i += 256) { float g = g_gW1[i]; s += g*g; }
    for (int i = t; i < NHD;     i += 256) { float g = g_gb1[i]; s += g*g; }
    for (int i = t; i < NVD*NHD; i += 256) { float g = g_gW2[i]; s += g*g; }
    for (int i = t; i < NVD;     i += 256) { float g = g_gb2[i]; s += g*g; }
    red[t] = s; __syncthreads();
    for (int st = 128; st > 0; st >>= 1) { if (t < st) red[t] += red[t+st]; __syncthreads(); }
    if (t == 0) {
        float avg = sqrtf(red[0] * 0.25f);
        g_theta[0] = 0.1f / (1.f + expf(-avg));
    }
}

__global__ void update_k(const float* __restrict__ mW1, const float* __restrict__ mb1,
                         const float* __restrict__ mW2, const float* __restrict__ mb2,
                         const float* __restrict__ bW1, const float* __restrict__ bb1,
                         const float* __restrict__ bW2, const float* __restrict__ bb2)
{
    int i = blockIdx.x * 256 + threadIdx.x;
    float et = g_theta[0];
    const int n1 = NHD*NKD, n2 = n1 + NHD, n3 = n2 + NVD*NHD, n4 = n3 + NVD;
    if (i < n1)       g_nW1[i]   = 0.9f*mW1[i]   + 0.9f*bW1[i]   - et*g_gW1[i];
    else if (i < n2) { int j=i-n1; g_nb1[j] = 0.9f*mb1[j] + 0.9f*bb1[j] - et*g_gb1[j]; }
    else if (i < n3) { int j=i-n2; g_nW2[j] = 0.9f*mW2[j] + 0.9f*bW2[j] - et*g_gW2[j]; }
    else if (i < n4) { int j=i-n3; g_nb2[j] = 0.9f*mb2[j] + 0.9f*bb2[j] - et*g_gb2[j]; }
}

// softmax over rows [roff, roff+grid) of g_S; emits P fp16
__launch_bounds__(256)
__global__ void softmax_k(int roff)
{
    const int r = blockIdx.x + roff;
    const float* row = g_S + (size_t)r * NH;
    fp16* op = g_attnP + (size_t)r * NH;
    const int t = threadIdx.x;
    float v[64];
    float m = -1e30f;
    #pragma unroll
    for (int j = 0; j < 64; j++) { v[j] = row[t + 256*j]; m = fmaxf(m, v[j]); }
    __shared__ float red[256];
    red[t] = m; __syncthreads();
    #pragma unroll
    for (int s = 128; s > 0; s >>= 1) { if (t < s) red[t] = fmaxf(red[t], red[t+s]); __syncthreads(); }
    m = red[0]; __syncthreads();
    float l = 0.f;
    #pragma unroll
    for (int j = 0; j < 64; j++) { v[j] = __expf(v[j] - m); l += v[j]; }
    red[t] = l; __syncthreads();
    #pragma unroll
    for (int s = 128; s > 0; s >>= 1) { if (t < s) red[t] += red[t+s]; __syncthreads(); }
    float inv = 1.f / red[0];
    #pragma unroll
    for (int j = 0; j < 64; j++)
        op[t + 256*j] = __float2half(v[j] * inv);
}

__global__ void entity_k(const float* __restrict__ ent, const float* __restrict__ Wep,
                         const float* __restrict__ bep, const float* __restrict__ Weg,
                         const float* __restrict__ beg)
{
    __shared__ float eavg[DIN];
    __shared__ float ectx[NVD];
    int t = threadIdx.x;
    float s = 0.f;
    for (int e = 0; e < NE; e++) s += ent[e*DIN + t];
    eavg[t] = s * (1.f / NE);
    __syncthreads();
    if (t < NVD) {
        float c = bep[t];
        for (int d = 0; d < DIN; d++) c += eavg[d] * Wep[t*DIN + d];
        ectx[t] = c; g_ectx[t] = c;
    }
    __syncthreads();
    if (t == 0) {
        float g = beg[0];
        for (int j = 0; j < NVD; j++) g += ectx[j] * Weg[j];
        g_eg[0] = 1.f / (1.f + expf(-g));
    }
}

__global__ void fuse_k(const float* __restrict__ kvec, const float* __restrict__ Wg,
                       const float* __restrict__ bg, const float* __restrict__ bst,
                       float* __restrict__ out)
{
    int b = blockIdx.x, i = threadIdx.x;
    float p = g_ctx[b*NVD + i] + kvec[i];
    float s = p * Wg[i];
    #pragma unroll
    for (int o = 16; o > 0; o >>= 1) s += __shfl_down_sync(0xffffffffu, s, o);
    __shared__ float wsum[4];
    __shared__ float gsh;
    if ((i & 31) == 0) wsum[i >> 5] = s;
    __syncthreads();
    if (i == 0) {
        float tot = wsum[0] + wsum[1] + wsum[2] + wsum[3] + bg[0];
        gsh = 1.f / (1.f + expf(-tot));
    }
    __syncthreads();
    float gate = gsh;
    float st = g_st[b*NVD + i] + bst[i];
    float f = gate * p + (1.f - gate) * st;
    float eg = g_eg[0];
    out[b*NVD + i] = eg * g_ectx[i] + (1.f - eg) * f;
}

// ================= host =================
extern "C" void kernel_launch(void* const* d_in, const int* in_sizes, int n_in,
                              void* d_out, int out_size)
{
    const float* x     = (const float*)d_in[0];
    const float* hist  = (const float*)d_in[1];
    const float* ent   = (const float*)d_in[2];
    const float* W_K   = (const float*)d_in[3];
    const float* W_V   = (const float*)d_in[4];
    const float* mW1   = (const float*)d_in[5];
    const float* mb1   = (const float*)d_in[6];
    const float* mW2   = (const float*)d_in[7];
    const float* mb2   = (const float*)d_in[8];
    const float* bufW1 = (const float*)d_in[9];
    const float* bufb1 = (const float*)d_in[10];
    const float* bufW2 = (const float*)d_in[11];
    const float* bufb2 = (const float*)d_in[12];
    const float* kvec  = (const float*)d_in[13];
    const float* Wq    = (const float*)d_in[14];
    const float* Wk    = (const float*)d_in[15];
    const float* Wst   = (const float*)d_in[16];
    const float* bst   = (const float*)d_in[17];
    const float* Wg    = (const float*)d_in[18];
    const float* bg    = (const float*)d_in[19];
    const float* Wep   = (const float*)d_in[24];
    const float* bep   = (const float*)d_in[25];
    const float* Weg   = (const float*)d_in[26];
    const float* beg   = (const float*)d_in[27];
    float* out = (float*)d_out;

    static bool init_done = false;
    static cudaStream_t s2, s3;
    static cudaEvent_t ev_fork, ev_join, ev_prep, ev_qf, ev_q, ev_hwt;
    static cudaEvent_t ev_s0, ev_f0, ev_f1, ev_ah0, ev_titan;
    if (!init_done) {
        cudaFuncSetAttribute((const void*)hmma_gemm<0,0>, cudaFuncAttributeMaxDynamicSharedMemorySize, HM_SMEM);
        cudaFuncSetAttribute((const void*)hmma_gemm<3,0>, cudaFuncAttributeMaxDynamicSharedMemorySize, HM_SMEM);
        cudaFuncSetAttribute((const void*)hmma_gemm<0,2>, cudaFuncAttributeMaxDynamicSharedMemorySize, HM_SMEM);
        cudaStreamCreateWithFlags(&s2, cudaStreamNonBlocking);
        cudaStreamCreateWithFlags(&s3, cudaStreamNonBlocking);
        cudaEventCreateWithFlags(&ev_fork, cudaEventDisableTiming);
        cudaEventCreateWithFlags(&ev_join, cudaEventDisableTiming);
        cudaEventCreateWithFlags(&ev_prep, cudaEventDisableTiming);
        cudaEventCreateWithFlags(&ev_qf,   cudaEventDisableTiming);
        cudaEventCreateWithFlags(&ev_q,    cudaEventDisableTiming);
        cudaEventCreateWithFlags(&ev_hwt,  cudaEventDisableTiming);
        cudaEventCreateWithFlags(&ev_s0,   cudaEventDisableTiming);
        cudaEventCreateWithFlags(&ev_f0,   cudaEventDisableTiming);
        cudaEventCreateWithFlags(&ev_f1,   cudaEventDisableTiming);
        cudaEventCreateWithFlags(&ev_ah0,  cudaEventDisableTiming);
        cudaEventCreateWithFlags(&ev_titan,cudaEventDisableTiming);
        init_done = true;
    }

    float *pk,*pv,*ph,*pdp,*pdh,*pgW1p,*pgW2p,*pgW1,*pgb1,*pgW2,*pgb2;
    float *pnW1,*pnb1,*pnW2,*pnb2,*ph2,*pctx,*pS,*paop,*pst,*pWT,*pqf;
    bf16 *pWsth,*pWstl,*phh,*phl,*pqh,*pql;
    fp16 *phwTh,*pP;
    cudaGetSymbolAddress((void**)&pk,   g_k);
    cudaGetSymbolAddress((void**)&pv,   g_v);
    cudaGetSymbolAddress((void**)&ph,   g_h);
    cudaGetSymbolAddress((void**)&pdp,  g_dpred);
    cudaGetSymbolAddress((void**)&pdh,  g_dh);
    cudaGetSymbolAddress((void**)&pgW1p,g_gW1p);
    cudaGetSymbolAddress((void**)&pgW2p,g_gW2p);
    cudaGetSymbolAddress((void**)&pgW1, g_gW1);
    cudaGetSymbolAddress((void**)&pgb1, g_gb1);
    cudaGetSymbolAddress((void**)&pgW2, g_gW2);
    cudaGetSymbolAddress((void**)&pgb2, g_gb2);
    cudaGetSymbolAddress((void**)&pnW1, g_nW1);
    cudaGetSymbolAddress((void**)&pnb1, g_nb1);
    cudaGetSymbolAddress((void**)&pnW2, g_nW2);
    cudaGetSymbolAddress((void**)&pnb2, g_nb2);
    cudaGetSymbolAddress((void**)&ph2,  g_h2);
    cudaGetSymbolAddress((void**)&pctx, g_ctx);
    cudaGetSymbolAddress((void**)&pS,   g_S);
    cudaGetSymbolAddress((void**)&paop, g_aop);
    cudaGetSymbolAddress((void**)&pst,  g_st);
    cudaGetSymbolAddress((void**)&pWT,  g_WT);
    cudaGetSymbolAddress((void**)&pqf,  g_qf);
    cudaGetSymbolAddress((void**)&pWsth,g_Wsth);
    cudaGetSymbolAddress((void**)&pWstl,g_Wstl);
    cudaGetSymbolAddress((void**)&phh,  g_histh);
    cudaGetSymbolAddress((void**)&phl,  g_histl);
    cudaGetSymbolAddress((void**)&phwTh,g_hwTh);
    cudaGetSymbolAddress((void**)&pqh,  g_qh);
    cudaGetSymbolAddress((void**)&pql,  g_ql);
    cudaGetSymbolAddress((void**)&pP,   g_attnP);

    // fork streams
    cudaEventRecord(ev_fork, 0);
    cudaStreamWaitEvent(s2, ev_fork, 0);
    cudaStreamWaitEvent(s3, ev_fork, 0);

    // ===== stream s2: Titan memory chain + entity (fp32 FFMA) =====
    gemm_abT<false,false,false><<<dim3(NKD/64, NB/64), 256, 0, s2>>>(
        x, W_K, nullptr, nullptr, 0.f, pk, NB, NKD, DIN);
    gemm_abT<false,false,false><<<dim3(NVD/64, NB/64), 256, 0, s2>>>(
        x, W_V, nullptr, nullptr, 0.f, pv, NB, NVD, DIN);
    gemm_abT<true,true,false><<<dim3(NHD/64, NB/64), 256, 0, s2>>>(
        pk, mW1, mb1, nullptr, 0.f, ph, NB, NHD, NKD);
    gemm_abT<true,false,true><<<dim3(NVD/64, NB/64), 256, 0, s2>>>(
        ph, mW2, mb2, pv, 2.f / (float)(NB*NVD), pdp, NB, NVD, NHD);
    gemm_aTb<<<dim3(NHD/64, NVD/64, NSPLIT_G), 256, 0, s2>>>(pdp, ph, pgW2p, NB, NVD, NHD, NB/NSPLIT_G);
    combine_k<<<(NVD*NHD + 255)/256, 256, 0, s2>>>(pgW2p, pgW2, NVD*NHD, NSPLIT_G);
    colsum_k<<<1, NVD, 0, s2>>>(pdp, pgb2, NB, NVD);
    gemm_ab<true><<<dim3(NHD/64, NB/64, 1), 256, 0, s2>>>(pdp, mW2, ph, pdh, NB, NHD, NVD, NVD);
    colsum_k<<<1, NHD, 0, s2>>>(pdh, pgb1, NB, NHD);
    gemm_aTb<<<dim3(NKD/64, NHD/64, NSPLIT_G), 256, 0, s2>>>(pdh, pk, pgW1p, NB, NHD, NKD, NB/NSPLIT_G);
    combine_k<<<(NHD*NKD + 255)/256, 256, 0, s2>>>(pgW1p, pgW1, NHD*NKD, NSPLIT_G);
    surprise_k<<<1, 256, 0, s2>>>();
    update_k<<<(NHD*NKD + NHD + NVD*NHD + NVD + 255)/256, 256, 0, s2>>>(
        mW1, mb1, mW2, mb2, bufW1, bufb1, bufW2, bufb2);
    gemm_abT<true,true,false><<<dim3(NHD/64, NB/64), 256, 0, s2>>>(
        pk, pnW1, pnb1, nullptr, 0.f, ph2, NB, NHD, NKD);
    gemm_abT<true,false,false><<<dim3(NVD/64, NB/64), 256, 0, s2>>>(
        ph2, pnW2, pnb2, nullptr, 0.f, pctx, NB, NVD, NHD);
    entity_k<<<1, DIN, 0, s2>>>(ent, Wep, bep, Weg, beg);
    cudaEventRecord(ev_join, s2);

    // ===== stream0: splits (Wst, hist) =====
    split_k<<<(NVD*DIN + 255)/256, 256>>>(Wst, pWsth, pWstl, NVD*DIN);
    split_k<<<(NH*DIN + 255)/256, 256>>>(hist, phh, phl, NH*DIN);
    cudaEventRecord(ev_prep, 0);

    // ===== stream s3: W' gemm, q' fp32 (exact), q' split, hwT =====
    gemm_aTb<<<dim3(DIN/64, DIN/64, 1), 256, 0, s3>>>(Wk, Wq, pWT, DIN, DIN, DIN, DIN);
    gemm_abT<false,false,false><<<dim3(DIN/64, NB/64), 256, 0, s3>>>(
        x, pWT, nullptr, nullptr, 0.f, pqf, NB, DIN, DIN);
    cudaEventRecord(ev_qf, s3);                                    // record BEFORE any wait on it
    split_k<<<(NB*DIN + 255)/256, 256, 0, s3>>>(pqf, pqh, pql, NB*DIN);
    cudaEventRecord(ev_q, s3);
    cudaStreamWaitEvent(s3, ev_prep, 0);
    // hwT = Wst @ hist^T -> fp16, [NVD, NH] (bf16 3-term compute)
    hmma_gemm<3,0><<<dim3(NH/128, NVD/128, 1), 512, HM_SMEM, s3>>>(
        pWsth, pWstl, phh, phl, nullptr, (unsigned short*)phwTh,
        NVD, NH, DIN, DIN, 0);
    cudaEventRecord(ev_hwt, s3);

    // ===== stream s2 (appended after titan): FFMA S-slice, cols [NT, NH) =====
    cudaStreamWaitEvent(s2, ev_qf, 0);      // ev_qf already recorded above — capture-legal
    gemm_abT_s<<<dim3(NF/64, 16), 256, 0, s2>>>(pqf, hist, pS, NH, DIN, NT, 0);
    cudaEventRecord(ev_f0, s2);
    gemm_abT_s<<<dim3(NF/64, 16), 256, 0, s2>>>(pqf, hist, pS, NH, DIN, NT, 1024);
    cudaEventRecord(ev_f1, s2);

    // ===== 2-chunk pipelined tensor-S (cols [0,NT)) -> softmax -> AH =====
    cudaStreamWaitEvent(0, ev_q, 0);
    hmma_gemm<0,0><<<dim3(NT/128, 8, 1), 512, HM_SMEM>>>(
        pqh, pql, phh, phl, pS, nullptr, NB, NH, DIN, DIN, 0);
    cudaEventRecord(ev_s0, 0);

    // chunk0 softmax + AH (1-term fp16) on s3, after tensor-S0 + FFMA-S0 + hwT
    cudaStreamWaitEvent(s3, ev_s0, 0);
    cudaStreamWaitEvent(s3, ev_f0, 0);
    softmax_k<<<1024, 256, 0, s3>>>(0);
    hmma_gemm<0,2><<<dim3(NVD/128, 8, NSPLIT_AH), 512, HM_SMEM, s3>>>(
        (const bf16*)pP, nullptr, (const bf16*)phwTh, nullptr,
        paop, nullptr, NB, NVD, NH, NH/NSPLIT_AH, 0);
    cudaEventRecord(ev_ah0, s3);

    // chunk1 on stream0
    hmma_gemm<0,0><<<dim3(NT/128, 8, 1), 512, HM_SMEM>>>(
        pqh, pql, phh, phl, pS, nullptr, NB, NH, DIN, DIN, 1024);
    cudaStreamWaitEvent(0, ev_f1, 0);
    softmax_k<<<1024, 256>>>(1024);
    cudaStreamWaitEvent(0, ev_hwt, 0);
    hmma_gemm<0,2><<<dim3(NVD/128, 8, NSPLIT_AH), 512, HM_SMEM>>>(
        (const bf16*)pP, nullptr, (const bf16*)phwTh, nullptr,
        paop, nullptr, NB, NVD, NH, NH/NSPLIT_AH, 1024);

    // combine both chunks' slabs
    cudaStreamWaitEvent(0, ev_ah0, 0);
    combine_k<<<(NB*NVD + 255)/256, 256>>>(paop, pst, NB*NVD, NSPLIT_AH);

    // join + fuse
    cudaStreamWaitEvent(0, ev_join, 0);
    fuse_k<<<NB, NVD>>>(kvec, Wg, bg, bst, out);
}

// round 16
// speedup vs baseline: 1.2499x; 1.2499x over previous
#include <cuda_runtime.h>
#include <cuda_bf16.h>
#include <cuda_fp16.h>
#include <math.h>
#include <stdint.h>

// Problem dims
#define NB   2048
#define NH   16384
#define NE   64
#define DIN  384
#define NKD  128
#define NVD  128
#define NHD  256
#define NSPLIT_G 8
#define NSPLIT_AH 16

typedef __nv_bfloat16 bf16;
typedef __half fp16;

// ---------------- scratch (device globals) ----------------
__device__ float g_k[NB*NKD];
__device__ float g_v[NB*NVD];
__device__ float g_h[NB*NHD];
__device__ float g_dpred[NB*NVD];
__device__ float g_dh[NB*NHD];
__device__ float g_gW1p[NSPLIT_G*NHD*NKD];
__device__ float g_gW2p[NSPLIT_G*NVD*NHD];
__device__ float g_gW1[NHD*NKD];
__device__ float g_gb1[NHD];
__device__ float g_gW2[NVD*NHD];
__device__ float g_gb2[NVD];
__device__ float g_nW1[NHD*NKD];
__device__ float g_nb1[NHD];
__device__ float g_nW2[NVD*NHD];
__device__ float g_nb2[NVD];
__device__ float g_h2[NB*NHD];
__device__ float g_ctx[NB*NVD];
__device__ float g_S[33554432];            // 2048*16384 fp32
__device__ float g_aop[NSPLIT_AH*NB*NVD];
__device__ float g_st[NB*NVD];
__device__ float g_WT[DIN*DIN];            // W'^T = Wk^T @ Wq (fp32)
__device__ float g_theta[1];
__device__ float g_ectx[NVD];
__device__ float g_eg[1];
// split operands
__device__ bf16 g_xh[NB*DIN],   g_xl[NB*DIN];
__device__ bf16 g_WTh[DIN*DIN], g_WTl[DIN*DIN];
__device__ bf16 g_Wsth[NVD*DIN], g_Wstl[NVD*DIN];
__device__ bf16 g_histh[NH*DIN], g_histl[NH*DIN];
__device__ fp16 g_hwTh[(size_t)NVD*NH], g_hwTl[(size_t)NVD*NH];  // (Wst @ hist^T) fp16 split
__device__ bf16 g_qh[NB*DIN],   g_ql[NB*DIN];                    // q' = x @ W'
__device__ fp16 g_attnP[(size_t)NB*NH];                          // P fp16 (unsplit)

// ================= HMMA (mma.sync) GEMM =================
// AMODE 0: C = Ah@Bh^T + Ah@Bl^T + Al@Bh^T (bf16 3-term)
// AMODE 1: C = A@Bh^T + A@Bl^T             (fp16 2-term, A unsplit)
// WMODE 0: fp32 -> Cf + z*M*N; 1: bf16 hi/lo; 2: fp16 hi/lo
// CTA tile 128x128xK32, 512 threads (16 warps: 4m x 4n, warp tile 32x32),
// 3-stage cp.async, ONE __syncthreads per iter, ldmatrix, 80B padded rows,
// term-major MMA order. moff = extra M-row offset (chunked launches).

#define TILE_B   10240
#define STAGE_B  (4*TILE_B)
#define NSTAGE   3
#define HM_SMEM  (NSTAGE*STAGE_B)   // 122880

__device__ __forceinline__ uint32_t smem_u32(const void* p) {
    uint32_t a;
    asm("{ .reg .u64 t; cvta.to.shared.u64 t, %1; cvt.u32.u64 %0, t; }" : "=r"(a) : "l"(p));
    return a;
}
__device__ __forceinline__ void cp16(uint32_t s, const void* g) {
    asm volatile("cp.async.cg.shared.global [%0], [%1], 16;" :: "r"(s), "l"(g));
}
__device__ __forceinline__ void cp_commit() {
    asm volatile("cp.async.commit_group;" ::: "memory");
}
template<int N>
__device__ __forceinline__ void cp_wait() {
    asm volatile("cp.async.wait_group %0;" :: "n"(N) : "memory");
}
__device__ __forceinline__ void ldsm4(uint32_t* r, uint32_t addr) {
    asm volatile("ldmatrix.sync.aligned.m8n8.x4.shared.b16 {%0,%1,%2,%3}, [%4];"
                 : "=r"(r[0]), "=r"(r[1]), "=r"(r[2]), "=r"(r[3]) : "r"(addr));
}
__device__ __forceinline__ void ldsm2(uint32_t* r, uint32_t addr) {
    asm volatile("ldmatrix.sync.aligned.m8n8.x2.shared.b16 {%0,%1}, [%2];"
                 : "=r"(r[0]), "=r"(r[1]) : "r"(addr));
}
__device__ __forceinline__ void mma_bf16(float* c, const uint32_t* a, const uint32_t* b) {
    asm volatile(
        "mma.sync.aligned.m16n8k16.row.col.f32.bf16.bf16.f32 "
        "{%0,%1,%2,%3}, {%4,%5,%6,%7}, {%8,%9}, {%0,%1,%2,%3};"
        : "+f"(c[0]), "+f"(c[1]), "+f"(c[2]), "+f"(c[3])
        : "r"(a[0]), "r"(a[1]), "r"(a[2]), "r"(a[3]), "r"(b[0]), "r"(b[1]));
}
__device__ __forceinline__ void mma_f16(float* c, const uint32_t* a, const uint32_t* b) {
    asm volatile(
        "mma.sync.aligned.m16n8k16.row.col.f32.f16.f16.f32 "
        "{%0,%1,%2,%3}, {%4,%5,%6,%7}, {%8,%9}, {%0,%1,%2,%3};"
        : "+f"(c[0]), "+f"(c[1]), "+f"(c[2]), "+f"(c[3])
        : "r"(a[0]), "r"(a[1]), "r"(a[2]), "r"(a[3]), "r"(b[0]), "r"(b[1]));
}

template<int WMODE>
__device__ __forceinline__ void split_store(float v, unsigned short& h, unsigned short& l) {
    if (WMODE == 2) {
        fp16 hh = __float2half(v);
        fp16 ll = __float2half(v - __half2float(hh));
        h = *(unsigned short*)&hh; l = *(unsigned short*)&ll;
    } else {
        bf16 hh = __float2bfloat16(v);
        bf16 ll = __float2bfloat16(v - __bfloat162float(hh));
        h = *(unsigned short*)&hh; l = *(unsigned short*)&ll;
    }
}

template<int WMODE, int AMODE>
__global__ void __launch_bounds__(512, 1) hmma_gemm(
    const bf16* __restrict__ Ah, const bf16* __restrict__ Al,
    const bf16* __restrict__ Bh, const bf16* __restrict__ Bl,
    float* __restrict__ Cf, unsigned short* __restrict__ Ch, unsigned short* __restrict__ Cl,
    int M, int N, int K, int Kchunk, int moff)
{
    extern __shared__ char smem[];
    const int tid = threadIdx.x, wid = tid >> 5, lid = tid & 31;
    const int wm = wid >> 2, wn = wid & 3;
    const int g = lid >> 2, t = lid & 3;
    const int n0 = blockIdx.x * 128, m0 = blockIdx.y * 128 + moff;
    const int kbeg = blockIdx.z * Kchunk;
    const int iters = Kchunk / 32;

    const uint32_t sb = smem_u32(smem);
    const bf16* srcs[4] = { Ah, Al, Bh, Bl };
    const int   rows[4] = { m0, m0, n0, n0 };

    const uint32_t a_off = (uint32_t)((wm*32 + (lid & 15)) * 80 + (lid >> 4) * 16);
    const uint32_t b_off = (uint32_t)((wn*32 + (lid & 7))  * 80 + ((lid >> 3) & 1) * 16);

    const int l_row = tid >> 2, l_ch = tid & 3;

    auto load_stage = [&](int stage, int k0) {
        uint32_t base = sb + stage * STAGE_B + l_row*80 + l_ch*16;
        size_t goff = (size_t)l_row * K + k0 + l_ch*8;
        #pragma unroll
        for (int tile = 0; tile < 4; tile++) {
            if (AMODE == 1 && tile == 1) continue;   // no A-lo tile
            cp16(base + tile*TILE_B, srcs[tile] + (size_t)rows[tile]*K + goff);
        }
    };

    float acc[2][4][4];
    #pragma unroll
    for (int a = 0; a < 2; a++)
        #pragma unroll
        for (int b = 0; b < 4; b++)
            #pragma unroll
            for (int c = 0; c < 4; c++) acc[a][b][c] = 0.f;

    load_stage(0, kbeg);
    cp_commit();
    if (iters > 1) load_stage(1, kbeg + 32);
    cp_commit();

    for (int it = 0; it < iters; it++) {
        cp_wait<1>();
        __syncthreads();
        if (it + 2 < iters) load_stage((it + 2) % NSTAGE, kbeg + (it + 2) * 32);
        cp_commit();

        const uint32_t stb = sb + (it % NSTAGE) * STAGE_B;
        #pragma unroll
        for (int kb = 0; kb < 2; kb++) {
            const uint32_t ko = kb * 32;
            uint32_t ah[2][4], al[2][4], bh[4][2], bl[4][2];
            #pragma unroll
            for (int mf = 0; mf < 2; mf++) {
                ldsm4(ah[mf], stb + a_off + mf*(16*80) + ko);
                if (AMODE == 0) ldsm4(al[mf], stb + TILE_B + a_off + mf*(16*80) + ko);
            }
            #pragma unroll
            for (int nf = 0; nf < 4; nf++) {
                ldsm2(bh[nf], stb + 2*TILE_B + b_off + nf*(8*80) + ko);
                ldsm2(bl[nf], stb + 3*TILE_B + b_off + nf*(8*80) + ko);
            }
            #pragma unroll
            for (int mf = 0; mf < 2; mf++)
                #pragma unroll
                for (int nf = 0; nf < 4; nf++) {
                    if (AMODE == 0) mma_bf16(acc[mf][nf], ah[mf], bh[nf]);
                    else            mma_f16 (acc[mf][nf], ah[mf], bh[nf]);
                }
            #pragma unroll
            for (int mf = 0; mf < 2; mf++)
                #pragma unroll
                for (int nf = 0; nf < 4; nf++) {
                    if (AMODE == 0) mma_bf16(acc[mf][nf], ah[mf], bl[nf]);
                    else            mma_f16 (acc[mf][nf], ah[mf], bl[nf]);
                }
            if (AMODE == 0) {
                #pragma unroll
                for (int mf = 0; mf < 2; mf++)
                    #pragma unroll
                    for (int nf = 0; nf < 4; nf++)
                        mma_bf16(acc[mf][nf], al[mf], bh[nf]);
            }
        }
    }

    #pragma unroll
    for (int mf = 0; mf < 2; mf++) {
        #pragma unroll
        for (int nf = 0; nf < 4; nf++) {
            int row0 = m0 + wm*32 + mf*16 + g;
            int col  = n0 + wn*32 + nf*8 + 2*t;
            float* c = acc[mf][nf];
            if (WMODE >= 1) {
                ushort2 u0, u1, v0, v1;
                split_store<WMODE>(c[0], u0.x, u1.x);
                split_store<WMODE>(c[1], u0.y, u1.y);
                split_store<WMODE>(c[2], v0.x, v1.x);
                split_store<WMODE>(c[3], v0.y, v1.y);
                *(ushort2*)&Ch[(size_t)row0 * N + col]     = u0;
                *(ushort2*)&Cl[(size_t)row0 * N + col]     = u1;
                *(ushort2*)&Ch[(size_t)(row0+8) * N + col] = v0;
                *(ushort2*)&Cl[(size_t)(row0+8) * N + col] = v1;
            } else {
                float* Co = Cf + (size_t)blockIdx.z * M * N;
                *(float2*)&Co[(size_t)row0 * N + col]     = make_float2(c[0], c[1]);
                *(float2*)&Co[(size_t)(row0+8) * N + col] = make_float2(c[2], c[3]);
            }
        }
    }
}

// ================= conversion kernel =================
__global__ void split_k(const float* __restrict__ in, bf16* __restrict__ hi,
                        bf16* __restrict__ lo, int n)
{
    int i = blockIdx.x * 256 + threadIdx.x;
    if (i < n) {
        float v = in[i];
        bf16 h = __float2bfloat16(v);
        hi[i] = h;
        lo[i] = __float2bfloat16(v - __bfloat162float(h));
    }
}

// ================= FFMA GEMMs (titan chain + W'T) =================
template<bool BIAS, bool RELU, bool DPRED>
__launch_bounds__(256)
__global__ void gemm_abT(const float* __restrict__ A, const float* __restrict__ Bm,
                         const float* __restrict__ bias, const float* __restrict__ Vm,
                         float dscale, float* __restrict__ C,
                         int M, int N, int K)
{
    __shared__ float As[16][64];
    __shared__ float Bs[16][64];
    const int t  = threadIdx.x;
    const int tx = t & 15, ty = t >> 4;
    const int m0 = blockIdx.y * 64, n0 = blockIdx.x * 64;
    const int lr = t >> 2;
    const int lc = (t & 3) << 2;
    float acc[4][4] = {};
    const float* Ag = A  + (size_t)(m0 + lr) * K + lc;
    const float* Bg = Bm + (size_t)(n0 + lr) * K + lc;
    for (int k0 = 0; k0 < K; k0 += 16) {
        float4 a4 = *(const float4*)(Ag + k0);
        float4 b4 = *(const float4*)(Bg + k0);
        As[lc+0][lr]=a4.x; As[lc+1][lr]=a4.y; As[lc+2][lr]=a4.z; As[lc+3][lr]=a4.w;
        Bs[lc+0][lr]=b4.x; Bs[lc+1][lr]=b4.y; Bs[lc+2][lr]=b4.z; Bs[lc+3][lr]=b4.w;
        __syncthreads();
        #pragma unroll
        for (int kk = 0; kk < 16; kk++) {
            float4 av = *(const float4*)&As[kk][ty<<2];
            float4 bv = *(const float4*)&Bs[kk][tx<<2];
            acc[0][0]+=av.x*bv.x; acc[0][1]+=av.x*bv.y; acc[0][2]+=av.x*bv.z; acc[0][3]+=av.x*bv.w;
            acc[1][0]+=av.y*bv.x; acc[1][1]+=av.y*bv.y; acc[1][2]+=av.y*bv.z; acc[1][3]+=av.y*bv.w;
            acc[2][0]+=av.z*bv.x; acc[2][1]+=av.z*bv.y; acc[2][2]+=av.z*bv.z; acc[2][3]+=av.z*bv.w;
            acc[3][0]+=av.w*bv.x; acc[3][1]+=av.w*bv.y; acc[3][2]+=av.w*bv.z; acc[3][3]+=av.w*bv.w;
        }
        __syncthreads();
    }
    #pragma unroll
    for (int u = 0; u < 4; u++) {
        const int m = m0 + (ty<<2) + u;
        float4 o;
        float* oc = (float*)&o;
        #pragma unroll
        for (int v = 0; v < 4; v++) {
            const int n = n0 + (tx<<2) + v;
            float val = acc[u][v];
            if (BIAS) val += bias[n];
            if (RELU) val = fmaxf(val, 0.f);
            if (DPRED) val = (val - Vm[(size_t)m * N + n]) * dscale;
            oc[v] = val;
        }
        *(float4*)&C[(size_t)m * N + n0 + (tx<<2)] = o;
    }
}

template<bool MASK>
__launch_bounds__(256)
__global__ void gemm_ab(const float* __restrict__ A, const float* __restrict__ Bm,
                        const float* __restrict__ mask, float* __restrict__ C,
                        int M, int N, int K, int Kchunk)
{
    __shared__ float As[16][64];
    __shared__ float Bs[16][64];
    const int t  = threadIdx.x;
    const int tx = t & 15, ty = t >> 4;
    const int m0 = blockIdx.y * 64, n0 = blockIdx.x * 64;
    const int kbeg = blockIdx.z * Kchunk, kend = kbeg + Kchunk;
    const int lrA = t >> 2,  lcA = (t & 3)  << 2;
    const int lrB = t >> 4,  lcB = (t & 15) << 2;
    float acc[4][4] = {};
    for (int k0 = kbeg; k0 < kend; k0 += 16) {
        float4 a4 = *(const float4*)&A [(size_t)(m0 + lrA) * K + k0 + lcA];
        float4 b4 = *(const float4*)&Bm[(size_t)(k0 + lrB) * N + n0 + lcB];
        As[lcA+0][lrA]=a4.x; As[lcA+1][lrA]=a4.y; As[lcA+2][lrA]=a4.z; As[lcA+3][lrA]=a4.w;
        *(float4*)&Bs[lrB][lcB] = b4;
        __syncthreads();
        #pragma unroll
        for (int kk = 0; kk < 16; kk++) {
            float4 av = *(const float4*)&As[kk][ty<<2];
            float4 bv = *(const float4*)&Bs[kk][tx<<2];
            acc[0][0]+=av.x*bv.x; acc[0][1]+=av.x*bv.y; acc[0][2]+=av.x*bv.z; acc[0][3]+=av.x*bv.w;
            acc[1][0]+=av.y*bv.x; acc[1][1]+=av.y*bv.y; acc[1][2]+=av.y*bv.z; acc[1][3]+=av.y*bv.w;
            acc[2][0]+=av.z*bv.x; acc[2][1]+=av.z*bv.y; acc[2][2]+=av.z*bv.z; acc[2][3]+=av.z*bv.w;
            acc[3][0]+=av.w*bv.x; acc[3][1]+=av.w*bv.y; acc[3][2]+=av.w*bv.z; acc[3][3]+=av.w*bv.w;
        }
        __syncthreads();
    }
    float* Co = C + (size_t)blockIdx.z * M * N;
    #pragma unroll
    for (int u = 0; u < 4; u++) {
        const int m = m0 + (ty<<2) + u;
        float4 o;
        float* oc = (float*)&o;
        #pragma unroll
        for (int v = 0; v < 4; v++) {
            float val = acc[u][v];
            if (MASK) val = (mask[(size_t)m * N + n0 + (tx<<2) + v] > 0.f) ? val : 0.f;
            oc[v] = val;
        }
        *(float4*)&Co[(size_t)m * N + n0 + (tx<<2)] = o;
    }
}

__launch_bounds__(256)
__global__ void gemm_aTb(const float* __restrict__ A, const float* __restrict__ Bm,
                         float* __restrict__ Cpart, int L, int M, int N, int Lchunk)
{
    __shared__ float As[16][64];
    __shared__ float Bs[16][64];
    const int t  = threadIdx.x;
    const int tx = t & 15, ty = t >> 4;
    const int m0 = blockIdx.y * 64, n0 = blockIdx.x * 64;
    const int l0b = blockIdx.z * Lchunk;
    const int lr = t >> 4, lc4 = (t & 15) << 2;
    float acc[4][4] = {};
    for (int l0 = l0b; l0 < l0b + Lchunk; l0 += 16) {
        *(float4*)&As[lr][lc4] = *(const float4*)&A [(size_t)(l0 + lr) * M + m0 + lc4];
        *(float4*)&Bs[lr][lc4] = *(const float4*)&Bm[(size_t)(l0 + lr) * N + n0 + lc4];
        __syncthreads();
        #pragma unroll
        for (int kk = 0; kk < 16; kk++) {
            float4 av = *(const float4*)&As[kk][ty<<2];
            float4 bv = *(const float4*)&Bs[kk][tx<<2];
            acc[0][0]+=av.x*bv.x; acc[0][1]+=av.x*bv.y; acc[0][2]+=av.x*bv.z; acc[0][3]+=av.x*bv.w;
            acc[1][0]+=av.y*bv.x; acc[1][1]+=av.y*bv.y; acc[1][2]+=av.y*bv.z; acc[1][3]+=av.y*bv.w;
            acc[2][0]+=av.z*bv.x; acc[2][1]+=av.z*bv.y; acc[2][2]+=av.z*bv.z; acc[2][3]+=av.z*bv.w;
            acc[3][0]+=av.w*bv.x; acc[3][1]+=av.w*bv.y; acc[3][2]+=av.w*bv.z; acc[3][3]+=av.w*bv.w;
        }
        __syncthreads();
    }
    float* Co = Cpart + (size_t)blockIdx.z * M * N;
    #pragma unroll
    for (int u = 0; u < 4; u++) {
        float4 o;
        float* oc = (float*)&o;
        #pragma unroll
        for (int v = 0; v < 4; v++) oc[v] = acc[u][v];
        *(float4*)&Co[(size_t)(m0 + (ty<<2) + u) * N + n0 + (tx<<2)] = o;
    }
}

// ================= small kernels =================
__global__ void combine_k(const float* __restrict__ parts, float* __restrict__ out,
                          int len, int np)
{
    int i = blockIdx.x * 256 + threadIdx.x;
    if (i < len) {
        float s = 0.f;
        for (int p = 0; p < np; p++) s += parts[(size_t)p * len + i];
        out[i] = s;
    }
}

__global__ void colsum_k(const float* __restrict__ A, float* __restrict__ out, int rows, int N)
{
    int c = threadIdx.x;
    float s = 0.f;
    for (int r = 0; r < rows; r++) s += A[(size_t)r * N + c];
    out[c] = s;
}

__global__ void surprise_k()
{
    __shared__ float red[256];
    int t = threadIdx.x;
    float s = 0.f;
    for (int i = t; i < NHD*NKD; i += 256) { float g = g_gW1[i]; s += g*g; }
    for (int i = t; i < NHD;     i += 256) { float g = g_gb1[i]; s += g*g; }
    for (int i = t; i < NVD*NHD; i += 256) { float g = g_gW2[i]; s += g*g; }
    for (int i = t; i < NVD;     i += 256) { float g = g_gb2[i]; s += g*g; }
    red[t] = s; __syncthreads();
    for (int st = 128; st > 0; st >>= 1) { if (t < st) red[t] += red[t+st]; __syncthreads(); }
    if (t == 0) {
        float avg = sqrtf(red[0] * 0.25f);
        g_theta[0] = 0.1f / (1.f + expf(-avg));
    }
}

__global__ void update_k(const float* __restrict__ mW1, const float* __restrict__ mb1,
                         const float* __restrict__ mW2, const float* __restrict__ mb2,
                         const float* __restrict__ bW1, const float* __restrict__ bb1,
                         const float* __restrict__ bW2, const float* __restrict__ bb2)
{
    int i = blockIdx.x * 256 + threadIdx.x;
    float et = g_theta[0];
    const int n1 = NHD*NKD, n2 = n1 + NHD, n3 = n2 + NVD*NHD, n4 = n3 + NVD;
    if (i < n1)       g_nW1[i]   = 0.9f*mW1[i]   + 0.9f*bW1[i]   - et*g_gW1[i];
    else if (i < n2) { int j=i-n1; g_nb1[j] = 0.9f*mb1[j] + 0.9f*bb1[j] - et*g_gb1[j]; }
    else if (i < n3) { int j=i-n2; g_nW2[j] = 0.9f*mW2[j] + 0.9f*bW2[j] - et*g_gW2[j]; }
    else if (i < n4) { int j=i-n3; g_nb2[j] = 0.9f*mb2[j] + 0.9f*bb2[j] - et*g_gb2[j]; }
}

// softmax over rows [roff, roff+grid) of g_S; emits P fp16 (unsplit)
__launch_bounds__(256)
__global__ void softmax_k(int roff)
{
    const int r = blockIdx.x + roff;
    const float* row = g_S + (size_t)r * NH;
    fp16* op = g_attnP + (size_t)r * NH;
    const int t = threadIdx.x;
    float v[64];
    float m = -1e30f;
    #pragma unroll
    for (int j = 0; j < 64; j++) { v[j] = row[t + 256*j]; m = fmaxf(m, v[j]); }
    __shared__ float red[256];
    red[t] = m; __syncthreads();
    #pragma unroll
    for (int s = 128; s > 0; s >>= 1) { if (t < s) red[t] = fmaxf(red[t], red[t+s]); __syncthreads(); }
    m = red[0]; __syncthreads();
    float l = 0.f;
    #pragma unroll
    for (int j = 0; j < 64; j++) { v[j] = __expf(v[j] - m); l += v[j]; }
    red[t] = l; __syncthreads();
    #pragma unroll
    for (int s = 128; s > 0; s >>= 1) { if (t < s) red[t] += red[t+s]; __syncthreads(); }
    float inv = 1.f / red[0];
    #pragma unroll
    for (int j = 0; j < 64; j++)
        op[t + 256*j] = __float2half(v[j] * inv);
}

__global__ void entity_k(const float* __restrict__ ent, const float* __restrict__ Wep,
                         const float* __restrict__ bep, const float* __restrict__ Weg,
                         const float* __restrict__ beg)
{
    __shared__ float eavg[DIN];
    __shared__ float ectx[NVD];
    int t = threadIdx.x;
    float s = 0.f;
    for (int e = 0; e < NE; e++) s += ent[e*DIN + t];
    eavg[t] = s * (1.f / NE);
    __syncthreads();
    if (t < NVD) {
        float c = bep[t];
        for (int d = 0; d < DIN; d++) c += eavg[d] * Wep[t*DIN + d];
        ectx[t] = c; g_ectx[t] = c;
    }
    __syncthreads();
    if (t == 0) {
        float g = beg[0];
        for (int j = 0; j < NVD; j++) g += ectx[j] * Weg[j];
        g_eg[0] = 1.f / (1.f + expf(-g));
    }
}

__global__ void fuse_k(const float* __restrict__ kvec, const float* __restrict__ Wg,
                       const float* __restrict__ bg, const float* __restrict__ bst,
                       float* __restrict__ out)
{
    int b = blockIdx.x, i = threadIdx.x;
    float p = g_ctx[b*NVD + i] + kvec[i];
    float s = p * Wg[i];
    #pragma unroll
    for (int o = 16; o > 0; o >>= 1) s += __shfl_down_sync(0xffffffffu, s, o);
    __shared__ float wsum[4];
    __shared__ float gsh;
    if ((i & 31) == 0) wsum[i >> 5] = s;
    __syncthreads();
    if (i == 0) {
        float tot = wsum[0] + wsum[1] + wsum[2] + wsum[3] + bg[0];
        gsh = 1.f / (1.f + expf(-tot));
    }
    __syncthreads();
    float gate = gsh;
    float st = g_st[b*NVD + i] + bst[i];
    float f = gate * p + (1.f - gate) * st;
    float eg = g_eg[0];
    out[b*NVD + i] = eg * g_ectx[i] + (1.f - eg) * f;
}

// ================= host =================
extern "C" void kernel_launch(void* const* d_in, const int* in_sizes, int n_in,
                              void* d_out, int out_size)
{
    const float* x     = (const float*)d_in[0];
    const float* hist  = (const float*)d_in[1];
    const float* ent   = (const float*)d_in[2];
    const float* W_K   = (const float*)d_in[3];
    const float* W_V   = (const float*)d_in[4];
    const float* mW1   = (const float*)d_in[5];
    const float* mb1   = (const float*)d_in[6];
    const float* mW2   = (const float*)d_in[7];
    const float* mb2   = (const float*)d_in[8];
    const float* bufW1 = (const float*)d_in[9];
    const float* bufb1 = (const float*)d_in[10];
    const float* bufW2 = (const float*)d_in[11];
    const float* bufb2 = (const float*)d_in[12];
    const float* kvec  = (const float*)d_in[13];
    const float* Wq    = (const float*)d_in[14];
    const float* Wk    = (const float*)d_in[15];
    const float* Wst   = (const float*)d_in[16];
    const float* bst   = (const float*)d_in[17];
    const float* Wg    = (const float*)d_in[18];
    const float* bg    = (const float*)d_in[19];
    const float* Wep   = (const float*)d_in[24];
    const float* bep   = (const float*)d_in[25];
    const float* Weg   = (const float*)d_in[26];
    const float* beg   = (const float*)d_in[27];
    float* out = (float*)d_out;

    static bool init_done = false;
    static cudaStream_t s2, s3;
    static cudaEvent_t ev_fork, ev_join, ev_prep, ev_q, ev_hwt, ev_s0, ev_ah0;
    if (!init_done) {
        cudaFuncSetAttribute((const void*)hmma_gemm<0,0>, cudaFuncAttributeMaxDynamicSharedMemorySize, HM_SMEM);
        cudaFuncSetAttribute((const void*)hmma_gemm<1,0>, cudaFuncAttributeMaxDynamicSharedMemorySize, HM_SMEM);
        cudaFuncSetAttribute((const void*)hmma_gemm<2,0>, cudaFuncAttributeMaxDynamicSharedMemorySize, HM_SMEM);
        cudaFuncSetAttribute((const void*)hmma_gemm<0,1>, cudaFuncAttributeMaxDynamicSharedMemorySize, HM_SMEM);
        cudaStreamCreateWithFlags(&s2, cudaStreamNonBlocking);
        cudaStreamCreateWithFlags(&s3, cudaStreamNonBlocking);
        cudaEventCreateWithFlags(&ev_fork, cudaEventDisableTiming);
        cudaEventCreateWithFlags(&ev_join, cudaEventDisableTiming);
        cudaEventCreateWithFlags(&ev_prep, cudaEventDisableTiming);
        cudaEventCreateWithFlags(&ev_q,    cudaEventDisableTiming);
        cudaEventCreateWithFlags(&ev_hwt,  cudaEventDisableTiming);
        cudaEventCreateWithFlags(&ev_s0,   cudaEventDisableTiming);
        cudaEventCreateWithFlags(&ev_ah0,  cudaEventDisableTiming);
        init_done = true;
    }

    float *pk,*pv,*ph,*pdp,*pdh,*pgW1p,*pgW2p,*pgW1,*pgb1,*pgW2,*pgb2;
    float *pnW1,*pnb1,*pnW2,*pnb2,*ph2,*pctx,*pS,*paop,*pst,*pWT;
    bf16 *pxh,*pxl,*pWTh,*pWTl,*pWsth,*pWstl,*phh,*phl,*pqh,*pql;
    fp16 *phwTh,*phwTl,*pP;
    cudaGetSymbolAddress((void**)&pk,   g_k);
    cudaGetSymbolAddress((void**)&pv,   g_v);
    cudaGetSymbolAddress((void**)&ph,   g_h);
    cudaGetSymbolAddress((void**)&pdp,  g_dpred);
    cudaGetSymbolAddress((void**)&pdh,  g_dh);
    cudaGetSymbolAddress((void**)&pgW1p,g_gW1p);
    cudaGetSymbolAddress((void**)&pgW2p,g_gW2p);
    cudaGetSymbolAddress((void**)&pgW1, g_gW1);
    cudaGetSymbolAddress((void**)&pgb1, g_gb1);
    cudaGetSymbolAddress((void**)&pgW2, g_gW2);
    cudaGetSymbolAddress((void**)&pgb2, g_gb2);
    cudaGetSymbolAddress((void**)&pnW1, g_nW1);
    cudaGetSymbolAddress((void**)&pnb1, g_nb1);
    cudaGetSymbolAddress((void**)&pnW2, g_nW2);
    cudaGetSymbolAddress((void**)&pnb2, g_nb2);
    cudaGetSymbolAddress((void**)&ph2,  g_h2);
    cudaGetSymbolAddress((void**)&pctx, g_ctx);
    cudaGetSymbolAddress((void**)&pS,   g_S);
    cudaGetSymbolAddress((void**)&paop, g_aop);
    cudaGetSymbolAddress((void**)&pst,  g_st);
    cudaGetSymbolAddress((void**)&pWT,  g_WT);
    cudaGetSymbolAddress((void**)&pxh,  g_xh);
    cudaGetSymbolAddress((void**)&pxl,  g_xl);
    cudaGetSymbolAddress((void**)&pWTh, g_WTh);
    cudaGetSymbolAddress((void**)&pWTl, g_WTl);
    cudaGetSymbolAddress((void**)&pWsth,g_Wsth);
    cudaGetSymbolAddress((void**)&pWstl,g_Wstl);
    cudaGetSymbolAddress((void**)&phh,  g_histh);
    cudaGetSymbolAddress((void**)&phl,  g_histl);
    cudaGetSymbolAddress((void**)&phwTh,g_hwTh);
    cudaGetSymbolAddress((void**)&phwTl,g_hwTl);
    cudaGetSymbolAddress((void**)&pqh,  g_qh);
    cudaGetSymbolAddress((void**)&pql,  g_ql);
    cudaGetSymbolAddress((void**)&pP,   g_attnP);

    // fork streams
    cudaEventRecord(ev_fork, 0);
    cudaStreamWaitEvent(s2, ev_fork, 0);
    cudaStreamWaitEvent(s3, ev_fork, 0);

    // ===== stream s2: Titan memory chain + entity path (fp32 FFMA) =====
    gemm_abT<false,false,false><<<dim3(NKD/64, NB/64), 256, 0, s2>>>(
        x, W_K, nullptr, nullptr, 0.f, pk, NB, NKD, DIN);
    gemm_abT<false,false,false><<<dim3(NVD/64, NB/64), 256, 0, s2>>>(
        x, W_V, nullptr, nullptr, 0.f, pv, NB, NVD, DIN);
    gemm_abT<true,true,false><<<dim3(NHD/64, NB/64), 256, 0, s2>>>(
        pk, mW1, mb1, nullptr, 0.f, ph, NB, NHD, NKD);
    gemm_abT<true,false,true><<<dim3(NVD/64, NB/64), 256, 0, s2>>>(
        ph, mW2, mb2, pv, 2.f / (float)(NB*NVD), pdp, NB, NVD, NHD);
    gemm_aTb<<<dim3(NHD/64, NVD/64, NSPLIT_G), 256, 0, s2>>>(pdp, ph, pgW2p, NB, NVD, NHD, NB/NSPLIT_G);
    combine_k<<<(NVD*NHD + 255)/256, 256, 0, s2>>>(pgW2p, pgW2, NVD*NHD, NSPLIT_G);
    colsum_k<<<1, NVD, 0, s2>>>(pdp, pgb2, NB, NVD);
    gemm_ab<true><<<dim3(NHD/64, NB/64, 1), 256, 0, s2>>>(pdp, mW2, ph, pdh, NB, NHD, NVD, NVD);
    colsum_k<<<1, NHD, 0, s2>>>(pdh, pgb1, NB, NHD);
    gemm_aTb<<<dim3(NKD/64, NHD/64, NSPLIT_G), 256, 0, s2>>>(pdh, pk, pgW1p, NB, NHD, NKD, NB/NSPLIT_G);
    combine_k<<<(NHD*NKD + 255)/256, 256, 0, s2>>>(pgW1p, pgW1, NHD*NKD, NSPLIT_G);
    surprise_k<<<1, 256, 0, s2>>>();
    update_k<<<(NHD*NKD + NHD + NVD*NHD + NVD + 255)/256, 256, 0, s2>>>(
        mW1, mb1, mW2, mb2, bufW1, bufb1, bufW2, bufb2);
    gemm_abT<true,true,false><<<dim3(NHD/64, NB/64), 256, 0, s2>>>(
        pk, pnW1, pnb1, nullptr, 0.f, ph2, NB, NHD, NKD);
    gemm_abT<true,false,false><<<dim3(NVD/64, NB/64), 256, 0, s2>>>(
        ph2, pnW2, pnb2, nullptr, 0.f, pctx, NB, NVD, NHD);
    entity_k<<<1, DIN, 0, s2>>>(ent, Wep, bep, Weg, beg);
    cudaEventRecord(ev_join, s2);

    // ===== stream0: splits (x, Wst, hist) =====
    split_k<<<(NB*DIN + 255)/256, 256>>>(x,    pxh,  pxl,  NB*DIN);
    split_k<<<(NVD*DIN + 255)/256, 256>>>(Wst, pWsth,pWstl,NVD*DIN);
    split_k<<<(NH*DIN + 255)/256, 256>>>(hist, phh,  phl,  NH*DIN);
    cudaEventRecord(ev_prep, 0);

    // ===== stream s3: W' gemm + split, q', hwT =====
    gemm_aTb<<<dim3(DIN/64, DIN/64, 1), 256, 0, s3>>>(Wk, Wq, pWT, DIN, DIN, DIN, DIN);
    split_k<<<(DIN*DIN + 255)/256, 256, 0, s3>>>(pWT, pWTh, pWTl, DIN*DIN);
    cudaStreamWaitEvent(s3, ev_prep, 0);
    hmma_gemm<1,0><<<dim3(DIN/128, NB/128, 1), 512, HM_SMEM, s3>>>(
        pxh, pxl, pWTh, pWTl, nullptr, (unsigned short*)pqh, (unsigned short*)pql,
        NB, DIN, DIN, DIN, 0);
    cudaEventRecord(ev_q, s3);
    // hwT = Wst @ hist^T -> fp16 split, [NVD, NH]
    hmma_gemm<2,0><<<dim3(NH/128, NVD/128, 1), 512, HM_SMEM, s3>>>(
        pWsth, pWstl, phh, phl, nullptr, (unsigned short*)phwTh, (unsigned short*)phwTl,
        NVD, NH, DIN, DIN, 0);
    cudaEventRecord(ev_hwt, s3);

    // ===== 2-chunk pipelined S -> softmax -> AH =====
    cudaStreamWaitEvent(0, ev_q, 0);
    hmma_gemm<0,0><<<dim3(NH/128, 8, 1), 512, HM_SMEM>>>(
        pqh, pql, phh, phl, pS, nullptr, nullptr, NB, NH, DIN, DIN, 0);
    cudaEventRecord(ev_s0, 0);

    // chunk0 softmax + AH on s3 (after hwT, ordered) while S chunk1 runs on stream0
    cudaStreamWaitEvent(s3, ev_s0, 0);
    softmax_k<<<1024, 256, 0, s3>>>(0);
    hmma_gemm<0,1><<<dim3(NVD/128, 8, NSPLIT_AH), 512, HM_SMEM, s3>>>(
        (const bf16*)pP, (const bf16*)pP, (const bf16*)phwTh, (const bf16*)phwTl,
        paop, nullptr, nullptr, NB, NVD, NH, NH/NSPLIT_AH, 0);
    cudaEventRecord(ev_ah0, s3);

    // chunk1 on stream0
    hmma_gemm<0,0><<<dim3(NH/128, 8, 1), 512, HM_SMEM>>>(
        pqh, pql, phh, phl, pS, nullptr, nullptr, NB, NH, DIN, DIN, 1024);
    softmax_k<<<1024, 256>>>(1024);
    cudaStreamWaitEvent(0, ev_hwt, 0);
    hmma_gemm<0,1><<<dim3(NVD/128, 8, NSPLIT_AH), 512, HM_SMEM>>>(
        (const bf16*)pP, (const bf16*)pP, (const bf16*)phwTh, (const bf16*)phwTl,
        paop, nullptr, nullptr, NB, NVD, NH, NH/NSPLIT_AH, 1024);

    // combine both chunks' slabs
    cudaStreamWaitEvent(0, ev_ah0, 0);
    combine_k<<<(NB*NVD + 255)/256, 256>>>(paop, pst, NB*NVD, NSPLIT_AH);

    // join + fuse
    cudaStreamWaitEvent(0, ev_join, 0);
    fuse_k<<<NB, NVD>>>(kvec, Wg, bg, bst, out);
}